// round 4
// baseline (speedup 1.0000x reference)
#include <cuda_runtime.h>
#include <cuda_fp16.h>
#include <cstdint>

#define BB     2048
#define TT     2049
#define SS     2048      // T-1
#define KK     8
#define CSZ    4         // cluster size
#define QT     512       // timesteps per CTA
#define NSEG   128       // segments per CTA
#define SEGLEN 4         // QT / NSEG
#define SPAD   40        // floats per segment in smem (32 data + 8 pad) -> conflict-free
#define GAMMA_F 0.99f

// smem layout (bytes):
//   s_  : NSEG*SPAD floats  = 20480   (q - Asuf)
//   mh  : NSEG*SPAD halves  = 10240   (Msuf, fp16)
//   sA  : NSEG*KK floats    = 4096
//   sM  : NSEG*KK floats    = 4096
//   sC  : NSEG*KK floats    = 4096
//   sAM : CSZ*KK floats     = 128     (per-rank CTA totals, rank0 only)
//   sMM : CSZ*KK floats     = 128
//   sXin: KK floats         = 32      (carry-in for this CTA)
//   red : 32 floats         = 128
#define SMEM_BYTES (NSEG*SPAD*4 + NSEG*SPAD*2 + 3*NSEG*KK*4 + 2*CSZ*KK*4 + KK*4 + 32*4)

__device__ __forceinline__ uint32_t smem_u32(const void* p) {
    uint32_t a;
    asm("{ .reg .u64 t; cvta.to.shared.u64 t, %1; cvt.u32.u64 %0, t; }"
        : "=r"(a) : "l"(p));
    return a;
}
__device__ __forceinline__ void dsmem_st_f32(uint32_t laddr, int rank, float v) {
    uint32_t raddr;
    asm("mapa.shared::cluster.u32 %0, %1, %2;" : "=r"(raddr) : "r"(laddr), "r"(rank));
    asm volatile("st.shared::cluster.f32 [%0], %1;" :: "r"(raddr), "f"(v) : "memory");
}

__global__ __launch_bounds__(256, 4) __cluster_dims__(CSZ, 1, 1)
void retrace_loss_kernel(const float* __restrict__ q,
                         const float* __restrict__ tq,
                         const float* __restrict__ tv,
                         const float* __restrict__ rw,
                         const float* __restrict__ olp,
                         const float* __restrict__ tlp,
                         float* __restrict__ out)
{
    extern __shared__ char smem[];
    float*  s_  = (float*)smem;                                   // NSEG*SPAD floats
    __half* mh  = (__half*)(s_ + NSEG * SPAD);                    // NSEG*SPAD halves
    float*  sA  = (float*)((char*)mh + NSEG * SPAD * 2);
    float*  sM  = sA + NSEG * KK;
    float*  sC  = sM + NSEG * KK;
    float*  sAM = sC + NSEG * KK;                                 // [CSZ][KK]
    float*  sMM = sAM + CSZ * KK;
    float*  sXin = sMM + CSZ * KK;
    float*  red  = sXin + KK;

    const int tid = threadIdx.x;
    const int kg  = tid & 1;        // 0,1 -> k range [kg*4, kg*4+4)
    const int seg = tid >> 1;       // 0..127

    uint32_t rank;
    asm("mov.u32 %0, %%cluster_ctarank;" : "=r"(rank));
    const int b = blockIdx.x >> 2;

    const size_t base3 = (size_t)b * TT * KK;
    const size_t base2 = (size_t)b * TT;
    const int tbase = (int)rank * QT + seg * SEGLEN;

    // ---------------- Phase 1: backward scan, float4 over k ----------------
    float4 A = make_float4(0.f, 0.f, 0.f, 0.f);
    float4 M = make_float4(1.f, 1.f, 1.f, 1.f);

    #pragma unroll
    for (int j = SEGLEN - 1; j >= 0; --j) {
        const int t = tbase + j;
        const size_t o0 = base3 + (size_t)t * KK + kg * 4;
        const size_t o1 = o0 + KK;

        const float4 r4  = *(const float4*)(rw  + o0);
        const float4 v4  = *(const float4*)(tv  + o1);
        const float4 Q4  = *(const float4*)(tq  + o1);
        const float4 l4  = *(const float4*)(tlp + o1);
        const float4 q4  = *(const float4*)(q   + o0);
        const float  ol  = olp[base2 + t + 1];

        const bool last = (t == SS - 1);
        const float sgn = last ? 1.0f : -1.0f;
        const float gm  = last ? 0.0f : GAMMA_F;

        float4 s4;
        {
            float c = __expf(fminf(l4.x - ol, 0.f));
            float a = fmaf(GAMMA_F, fmaf(sgn * c, Q4.x, v4.x), r4.x);
            float m = gm * c;
            A.x = fmaf(m, A.x, a); M.x *= m; s4.x = q4.x - A.x;
        }
        {
            float c = __expf(fminf(l4.y - ol, 0.f));
            float a = fmaf(GAMMA_F, fmaf(sgn * c, Q4.y, v4.y), r4.y);
            float m = gm * c;
            A.y = fmaf(m, A.y, a); M.y *= m; s4.y = q4.y - A.y;
        }
        {
            float c = __expf(fminf(l4.z - ol, 0.f));
            float a = fmaf(GAMMA_F, fmaf(sgn * c, Q4.z, v4.z), r4.z);
            float m = gm * c;
            A.z = fmaf(m, A.z, a); M.z *= m; s4.z = q4.z - A.z;
        }
        {
            float c = __expf(fminf(l4.w - ol, 0.f));
            float a = fmaf(GAMMA_F, fmaf(sgn * c, Q4.w, v4.w), r4.w);
            float m = gm * c;
            A.w = fmaf(m, A.w, a); M.w *= m; s4.w = q4.w - A.w;
        }

        const int si = seg * SPAD + j * KK + kg * 4;
        *(float4*)(s_ + si) = s4;
        __half2 h01 = __floats2half2_rn(M.x, M.y);
        __half2 h23 = __floats2half2_rn(M.z, M.w);
        uint2 hp;
        hp.x = *(uint32_t*)&h01;
        hp.y = *(uint32_t*)&h23;
        *(uint2*)(mh + si) = hp;
    }
    *(float4*)(sA + seg * KK + kg * 4) = A;
    *(float4*)(sM + seg * KK + kg * 4) = M;
    __syncthreads();

    // ---------------- CTA totals -> rank0 via DSMEM ----------------
    if (tid < KK) {
        float carry = 0.0f;
        #pragma unroll 1
        for (int s = NSEG - 1; s >= 0; --s)
            carry = fmaf(sM[s * KK + tid], carry, sA[s * KK + tid]);
        float Mtot = 1.0f;
        #pragma unroll 1
        for (int s = 0; s < NSEG; ++s)
            Mtot *= sM[s * KK + tid];
        dsmem_st_f32(smem_u32(&sAM[rank * KK + tid]), 0, carry);
        dsmem_st_f32(smem_u32(&sMM[rank * KK + tid]), 0, Mtot);
    }
    asm volatile("barrier.cluster.arrive.aligned;" ::: "memory");
    asm volatile("barrier.cluster.wait.aligned;"   ::: "memory");

    // ---------------- rank0: compose rank chain, scatter carry-ins ----------------
    if (rank == 0 && tid < KK) {
        float carry = 0.0f;
        uint32_t xin_l = smem_u32(&sXin[tid]);
        #pragma unroll 1
        for (int r = CSZ - 1; r >= 0; --r) {
            dsmem_st_f32(xin_l, r, carry);
            carry = fmaf(sMM[r * KK + tid], carry, sAM[r * KK + tid]);
        }
    }
    asm volatile("barrier.cluster.arrive.aligned;" ::: "memory");
    asm volatile("barrier.cluster.wait.aligned;"   ::: "memory");

    // ---------------- seeded per-segment carries ----------------
    if (tid < KK) {
        float carry = sXin[tid];
        sC[(NSEG - 1) * KK + tid] = carry;
        #pragma unroll 1
        for (int s = NSEG - 2; s >= 0; --s) {
            carry = fmaf(sM[(s + 1) * KK + tid], carry, sA[(s + 1) * KK + tid]);
            sC[s * KK + tid] = carry;
        }
    }
    __syncthreads();

    // ---------------- Phase 2: loss from smem ----------------
    const float4 c4 = *(const float4*)(sC + seg * KK + kg * 4);
    float lsum = 0.0f;
    #pragma unroll
    for (int j = 0; j < SEGLEN; ++j) {
        const int si = seg * SPAD + j * KK + kg * 4;
        const float4 s4 = *(const float4*)(s_ + si);
        const uint2  hp = *(const uint2*)(mh + si);
        const __half2 h01 = *(const __half2*)&hp.x;
        const __half2 h23 = *(const __half2*)&hp.y;
        const float2 m01 = __half22float2(h01);
        const float2 m23 = __half22float2(h23);

        float d, ad;
        d = fmaf(-m01.x, c4.x, s4.x); ad = fabsf(d);
        lsum += (ad < 1.0f) ? 0.5f * d * d : (ad - 0.5f);
        d = fmaf(-m01.y, c4.y, s4.y); ad = fabsf(d);
        lsum += (ad < 1.0f) ? 0.5f * d * d : (ad - 0.5f);
        d = fmaf(-m23.x, c4.z, s4.z); ad = fabsf(d);
        lsum += (ad < 1.0f) ? 0.5f * d * d : (ad - 0.5f);
        d = fmaf(-m23.y, c4.w, s4.w); ad = fabsf(d);
        lsum += (ad < 1.0f) ? 0.5f * d * d : (ad - 0.5f);
    }

    // ---------------- reduce + atomic ----------------
    #pragma unroll
    for (int off = 16; off > 0; off >>= 1)
        lsum += __shfl_down_sync(0xFFFFFFFFu, lsum, off);
    if ((tid & 31) == 0) red[tid >> 5] = lsum;
    __syncthreads();
    if (tid < 32) {
        float v = (tid < 8) ? red[tid] : 0.0f;
        #pragma unroll
        for (int off = 4; off > 0; off >>= 1)
            v += __shfl_down_sync(0xFFFFFFFFu, v, off);
        if (tid == 0)
            atomicAdd(out, v * (1.0f / 33554432.0f));  // mean over 2048*2048*8
    }
}

extern "C" void kernel_launch(void* const* d_in, const int* in_sizes, int n_in,
                              void* d_out, int out_size)
{
    (void)in_sizes; (void)n_in; (void)out_size;
    const float* q   = (const float*)d_in[0];
    const float* tq  = (const float*)d_in[1];
    const float* tv  = (const float*)d_in[2];
    const float* rw  = (const float*)d_in[3];
    const float* olp = (const float*)d_in[4];
    const float* tlp = (const float*)d_in[5];
    float* out = (float*)d_out;

    cudaFuncSetAttribute(retrace_loss_kernel,
                         cudaFuncAttributeMaxDynamicSharedMemorySize,
                         SMEM_BYTES);

    cudaMemsetAsync(out, 0, sizeof(float));
    retrace_loss_kernel<<<BB * CSZ, 256, SMEM_BYTES>>>(q, tq, tv, rw, olp, tlp, out);
}

// round 5
// speedup vs baseline: 1.2191x; 1.2191x over previous
#include <cuda_runtime.h>
#include <cuda_fp16.h>
#include <cstdint>

#define BB     2048
#define TT     2049
#define SS     2048      // T-1
#define KK     8
#define CSZ    2         // cluster size
#define QT     1024      // timesteps per CTA
#define NSEG   128       // segments per CTA (one per (tid>>1))
#define SEGLEN 8         // QT / NSEG
#define NW     8         // warps per CTA
#define ROW    (NSEG*KK) // 1024 floats per j-row (no padding needed, see layout note)
#define GAMMA_F 0.99f

// smem layout (bytes):
//   s_  : [SEGLEN][ROW] floats = 32768   (q - Asuf), index j*ROW + seg*8 + kg*4
//   mh  : [SEGLEN][ROW] halves = 16384   (Msuf fp16), same index
//   wA  : [NW][KK] floats      = 256     (warp-total A)
//   wM  : [NW][KK] floats      = 256     (warp-total M)
//   sXin: [KK] floats          = 32      (cluster seed, written only by rank1 via DSMEM)
//   red : [32] floats          = 128
// total = 49824 B -> 4 CTAs/SM (49824 -> 57344 after 8KB granularity; 4*57344 < 233472)
#define SMEM_BYTES (SEGLEN*ROW*4 + SEGLEN*ROW*2 + 2*NW*KK*4 + KK*4 + 32*4)

__device__ __forceinline__ uint32_t smem_u32(const void* p) {
    uint32_t a;
    asm("{ .reg .u64 t; cvta.to.shared.u64 t, %1; cvt.u32.u64 %0, t; }"
        : "=r"(a) : "l"(p));
    return a;
}

__global__ __launch_bounds__(256, 4) __cluster_dims__(CSZ, 1, 1)
void retrace_loss_kernel(const float* __restrict__ q,
                         const float* __restrict__ tq,
                         const float* __restrict__ tv,
                         const float* __restrict__ rw,
                         const float* __restrict__ olp,
                         const float* __restrict__ tlp,
                         float* __restrict__ out)
{
    extern __shared__ char smem[];
    float*  s_   = (float*)smem;                              // SEGLEN*ROW floats
    __half* mh   = (__half*)(s_ + SEGLEN * ROW);              // SEGLEN*ROW halves
    float*  wA   = (float*)((char*)mh + SEGLEN * ROW * 2);    // NW*KK
    float*  wM   = wA + NW * KK;
    float*  sXin = wM + NW * KK;                              // KK
    float*  red  = sXin + KK;                                 // 32

    const int tid  = threadIdx.x;
    const int kg   = tid & 1;            // k-group: floats [kg*4, kg*4+4)
    const int seg  = tid >> 1;           // 0..127
    const int lane = tid & 31;
    const int w    = tid >> 5;           // warp 0..7
    const int sl   = lane >> 1;          // seg within warp 0..15

    uint32_t rank;
    asm("mov.u32 %0, %%cluster_ctarank;" : "=r"(rank));
    const int b = blockIdx.x >> 1;

    const size_t base3 = (size_t)b * TT * KK;
    const size_t base2 = (size_t)b * TT;
    const int tbase = (int)rank * QT + seg * SEGLEN;

    // ---------------- Phase 1: backward scan over segment, float4 over k ----------------
    float4 A = make_float4(0.f, 0.f, 0.f, 0.f);
    float4 M = make_float4(1.f, 1.f, 1.f, 1.f);

    #pragma unroll 2
    for (int j = SEGLEN - 1; j >= 0; --j) {
        const int t = tbase + j;
        const size_t o0 = base3 + (size_t)t * KK + kg * 4;

        const float4 r4 = *(const float4*)(rw  + o0);
        const float4 v4 = *(const float4*)(tv  + o0 + KK);
        const float4 Q4 = *(const float4*)(tq  + o0 + KK);
        const float4 l4 = *(const float4*)(tlp + o0 + KK);
        const float4 q4 = *(const float4*)(q   + o0);
        const float  ol = olp[base2 + t + 1];

        const bool last = (t == SS - 1);
        const float sgn = last ? 1.0f : -1.0f;
        const float gm  = last ? 0.0f : GAMMA_F;

        float4 s4;
        { float c = __expf(fminf(l4.x - ol, 0.f));
          float a = fmaf(GAMMA_F, fmaf(sgn * c, Q4.x, v4.x), r4.x);
          float m = gm * c; A.x = fmaf(m, A.x, a); M.x *= m; s4.x = q4.x - A.x; }
        { float c = __expf(fminf(l4.y - ol, 0.f));
          float a = fmaf(GAMMA_F, fmaf(sgn * c, Q4.y, v4.y), r4.y);
          float m = gm * c; A.y = fmaf(m, A.y, a); M.y *= m; s4.y = q4.y - A.y; }
        { float c = __expf(fminf(l4.z - ol, 0.f));
          float a = fmaf(GAMMA_F, fmaf(sgn * c, Q4.z, v4.z), r4.z);
          float m = gm * c; A.z = fmaf(m, A.z, a); M.z *= m; s4.z = q4.z - A.z; }
        { float c = __expf(fminf(l4.w - ol, 0.f));
          float a = fmaf(GAMMA_F, fmaf(sgn * c, Q4.w, v4.w), r4.w);
          float m = gm * c; A.w = fmaf(m, A.w, a); M.w *= m; s4.w = q4.w - A.w; }

        const int si = j * ROW + seg * KK + kg * 4;
        *(float4*)(s_ + si) = s4;
        __half2 h01 = __floats2half2_rn(M.x, M.y);
        __half2 h23 = __floats2half2_rn(M.z, M.w);
        uint2 hp; hp.x = *(uint32_t*)&h01; hp.y = *(uint32_t*)&h23;
        *(uint2*)(mh + si) = hp;
    }

    // ---------------- Warp-level backward inclusive suffix scan over 16 segments ----------
    const unsigned fullm = 0xFFFFFFFFu;
    #pragma unroll
    for (int d = 1; d < 16; d <<= 1) {
        float4 Ao, Mo;
        Ao.x = __shfl_down_sync(fullm, A.x, 2 * d);
        Ao.y = __shfl_down_sync(fullm, A.y, 2 * d);
        Ao.z = __shfl_down_sync(fullm, A.z, 2 * d);
        Ao.w = __shfl_down_sync(fullm, A.w, 2 * d);
        Mo.x = __shfl_down_sync(fullm, M.x, 2 * d);
        Mo.y = __shfl_down_sync(fullm, M.y, 2 * d);
        Mo.z = __shfl_down_sync(fullm, M.z, 2 * d);
        Mo.w = __shfl_down_sync(fullm, M.w, 2 * d);
        if (sl + d < 16) {
            A.x = fmaf(M.x, Ao.x, A.x); M.x *= Mo.x;
            A.y = fmaf(M.y, Ao.y, A.y); M.y *= Mo.y;
            A.z = fmaf(M.z, Ao.z, A.z); M.z *= Mo.z;
            A.w = fmaf(M.w, Ao.w, A.w); M.w *= Mo.w;
        }
    }

    // Exclusive within warp: P_{sl+1..15}  (identity for sl==15)
    float4 PxA, PxM;
    PxA.x = __shfl_down_sync(fullm, A.x, 2);
    PxA.y = __shfl_down_sync(fullm, A.y, 2);
    PxA.z = __shfl_down_sync(fullm, A.z, 2);
    PxA.w = __shfl_down_sync(fullm, A.w, 2);
    PxM.x = __shfl_down_sync(fullm, M.x, 2);
    PxM.y = __shfl_down_sync(fullm, M.y, 2);
    PxM.z = __shfl_down_sync(fullm, M.z, 2);
    PxM.w = __shfl_down_sync(fullm, M.w, 2);
    if (sl == 15) {
        PxA = make_float4(0.f, 0.f, 0.f, 0.f);
        PxM = make_float4(1.f, 1.f, 1.f, 1.f);
    }

    // Warp totals (inclusive P at sl==0, i.e. lanes 0 and 1)
    if (lane < 2) {
        *(float4*)(wA + w * KK + kg * 4) = A;
        *(float4*)(wM + w * KK + kg * 4) = M;
    }
    __syncthreads();

    // ---------------- rank1: whole-CTA value applied to 0 -> DSMEM to rank0 --------------
    if (rank == 1 && tid < KK) {
        float x = 0.0f;
        #pragma unroll
        for (int ww = NW - 1; ww >= 0; --ww)
            x = fmaf(wM[ww * KK + tid], x, wA[ww * KK + tid]);
        uint32_t laddr = smem_u32(&sXin[tid]);
        uint32_t raddr;
        asm("mapa.shared::cluster.u32 %0, %1, %2;" : "=r"(raddr) : "r"(laddr), "r"(0));
        asm volatile("st.shared::cluster.f32 [%0], %1;" :: "r"(raddr), "f"(x) : "memory");
    }
    asm volatile("barrier.cluster.arrive.aligned;" ::: "memory");
    asm volatile("barrier.cluster.wait.aligned;"   ::: "memory");

    // ---------------- per-thread seed: compose later warps onto cluster seed -------------
    float4 x4;
    if (rank == 0) x4 = *(const float4*)(sXin + kg * 4);
    else           x4 = make_float4(0.f, 0.f, 0.f, 0.f);
    #pragma unroll
    for (int ww = NW - 1; ww > 0; --ww) {
        if (ww > w) {
            const float4 a4 = *(const float4*)(wA + ww * KK + kg * 4);
            const float4 m4 = *(const float4*)(wM + ww * KK + kg * 4);
            x4.x = fmaf(m4.x, x4.x, a4.x);
            x4.y = fmaf(m4.y, x4.y, a4.y);
            x4.z = fmaf(m4.z, x4.z, a4.z);
            x4.w = fmaf(m4.w, x4.w, a4.w);
        }
    }
    // carry entering this segment
    float4 c4;
    c4.x = fmaf(PxM.x, x4.x, PxA.x);
    c4.y = fmaf(PxM.y, x4.y, PxA.y);
    c4.z = fmaf(PxM.z, x4.z, PxA.z);
    c4.w = fmaf(PxM.w, x4.w, PxA.w);

    // ---------------- Phase 2: loss from smem: d = s - Msuf*carry ----------------
    float lsum = 0.0f;
    #pragma unroll
    for (int j = 0; j < SEGLEN; ++j) {
        const int si = j * ROW + seg * KK + kg * 4;
        const float4 s4 = *(const float4*)(s_ + si);
        const uint2  hp = *(const uint2*)(mh + si);
        const float2 m01 = __half22float2(*(const __half2*)&hp.x);
        const float2 m23 = __half22float2(*(const __half2*)&hp.y);

        float d, ad;
        d = fmaf(-m01.x, c4.x, s4.x); ad = fabsf(d);
        lsum += (ad < 1.0f) ? 0.5f * d * d : (ad - 0.5f);
        d = fmaf(-m01.y, c4.y, s4.y); ad = fabsf(d);
        lsum += (ad < 1.0f) ? 0.5f * d * d : (ad - 0.5f);
        d = fmaf(-m23.x, c4.z, s4.z); ad = fabsf(d);
        lsum += (ad < 1.0f) ? 0.5f * d * d : (ad - 0.5f);
        d = fmaf(-m23.y, c4.w, s4.w); ad = fabsf(d);
        lsum += (ad < 1.0f) ? 0.5f * d * d : (ad - 0.5f);
    }

    // ---------------- reduce + atomic ----------------
    #pragma unroll
    for (int off = 16; off > 0; off >>= 1)
        lsum += __shfl_down_sync(fullm, lsum, off);
    if (lane == 0) red[w] = lsum;
    __syncthreads();
    if (tid < 32) {
        float v = (tid < NW) ? red[tid] : 0.0f;
        #pragma unroll
        for (int off = 4; off > 0; off >>= 1)
            v += __shfl_down_sync(fullm, v, off);
        if (tid == 0)
            atomicAdd(out, v * (1.0f / 33554432.0f));  // mean over 2048*2048*8
    }
}

extern "C" void kernel_launch(void* const* d_in, const int* in_sizes, int n_in,
                              void* d_out, int out_size)
{
    (void)in_sizes; (void)n_in; (void)out_size;
    const float* q   = (const float*)d_in[0];
    const float* tq  = (const float*)d_in[1];
    const float* tv  = (const float*)d_in[2];
    const float* rw  = (const float*)d_in[3];
    const float* olp = (const float*)d_in[4];
    const float* tlp = (const float*)d_in[5];
    float* out = (float*)d_out;

    cudaFuncSetAttribute(retrace_loss_kernel,
                         cudaFuncAttributeMaxDynamicSharedMemorySize,
                         SMEM_BYTES);

    cudaMemsetAsync(out, 0, sizeof(float));
    retrace_loss_kernel<<<BB * CSZ, 256, SMEM_BYTES>>>(q, tq, tv, rw, olp, tlp, out);
}

// round 6
// speedup vs baseline: 1.9907x; 1.6329x over previous
#include <cuda_runtime.h>
#include <cuda_fp16.h>
#include <cstdint>

#define BB     2048
#define TT     2049
#define SS     2048      // T-1
#define KK     8
#define CSZ    2         // cluster size
#define QT     1024      // timesteps per CTA
#define WT     128       // timesteps per warp
#define NCH    8         // chunks per warp
#define CHT    16        // timesteps per chunk (warp-wide, 2 lanes per t)
#define NW     8
#define GAMMA_F 0.99f

// smem: s_ [QT*KK] f32 (32KB) | mh [QT*KK] f16 (16KB) | wA,wM [NW*KK] | sXin [KK] | red [32]
#define SMEM_BYTES (QT*KK*4 + QT*KK*2 + 2*NW*KK*4 + KK*4 + 32*4)

__device__ __forceinline__ uint32_t smem_u32(const void* p) {
    uint32_t a;
    asm("{ .reg .u64 t; cvta.to.shared.u64 t, %1; cvt.u32.u64 %0, t; }"
        : "=r"(a) : "l"(p));
    return a;
}

__global__ __launch_bounds__(256, 4) __cluster_dims__(CSZ, 1, 1)
void retrace_loss_kernel(const float* __restrict__ q,
                         const float* __restrict__ tq,
                         const float* __restrict__ tv,
                         const float* __restrict__ rw,
                         const float* __restrict__ olp,
                         const float* __restrict__ tlp,
                         float* __restrict__ out)
{
    extern __shared__ char smem[];
    float*  s_   = (float*)smem;                        // QT*KK f32
    __half* mh   = (__half*)(s_ + QT * KK);             // QT*KK f16
    float*  wA   = (float*)((char*)mh + QT * KK * 2);   // NW*KK
    float*  wM   = wA + NW * KK;
    float*  sXin = wM + NW * KK;                        // KK
    float*  red  = sXin + KK;

    const int tid  = threadIdx.x;
    const int lane = tid & 31;
    const int w    = tid >> 5;       // warp 0..7, owns t_local [w*128, w*128+128)
    const int sl   = lane >> 1;      // timestep within chunk 0..15
    const int kg   = lane & 1;       // k-group

    uint32_t rank;
    asm("mov.u32 %0, %%cluster_ctarank;" : "=r"(rank));
    const int b = blockIdx.x >> 1;

    const size_t base3 = (size_t)b * TT * KK;
    const size_t base2 = (size_t)b * TT;
    const unsigned fullm = 0xFFFFFFFFu;

    // running suffix relative to warp-region end
    float4 Ar = make_float4(0.f, 0.f, 0.f, 0.f);
    float4 Mr = make_float4(1.f, 1.f, 1.f, 1.f);

    #pragma unroll 2
    for (int ch = NCH - 1; ch >= 0; --ch) {
        const int tl = w * WT + ch * CHT + sl;          // local timestep
        const int t  = (int)rank * QT + tl;             // timestep in row
        const size_t o0 = base3 + (size_t)t * KK + kg * 4;

        // fully coalesced: warp covers 512 contiguous bytes per LDG.128
        const float4 r4 = *(const float4*)(rw  + o0);
        const float4 q4 = *(const float4*)(q   + o0);
        const float4 v4 = *(const float4*)(tv  + o0 + KK);
        const float4 Q4 = *(const float4*)(tq  + o0 + KK);
        const float4 l4 = *(const float4*)(tlp + o0 + KK);
        const float  ol = olp[base2 + t + 1];

        const bool last = (t == SS - 1);
        const float sgn = last ? 1.0f : -1.0f;
        const float gm  = last ? 0.0f : GAMMA_F;

        float4 A, M;
        { float c = __expf(fminf(l4.x - ol, 0.f));
          A.x = fmaf(GAMMA_F, fmaf(sgn * c, Q4.x, v4.x), r4.x); M.x = gm * c; }
        { float c = __expf(fminf(l4.y - ol, 0.f));
          A.y = fmaf(GAMMA_F, fmaf(sgn * c, Q4.y, v4.y), r4.y); M.y = gm * c; }
        { float c = __expf(fminf(l4.z - ol, 0.f));
          A.z = fmaf(GAMMA_F, fmaf(sgn * c, Q4.z, v4.z), r4.z); M.z = gm * c; }
        { float c = __expf(fminf(l4.w - ol, 0.f));
          A.w = fmaf(GAMMA_F, fmaf(sgn * c, Q4.w, v4.w), r4.w); M.w = gm * c; }

        // warp suffix scan over the 16 timesteps (lanes): x_sl = A + M * x_chunkend
        #pragma unroll
        for (int d = 1; d < 16; d <<= 1) {
            float4 Ao, Mo;
            Ao.x = __shfl_down_sync(fullm, A.x, 2 * d);
            Ao.y = __shfl_down_sync(fullm, A.y, 2 * d);
            Ao.z = __shfl_down_sync(fullm, A.z, 2 * d);
            Ao.w = __shfl_down_sync(fullm, A.w, 2 * d);
            Mo.x = __shfl_down_sync(fullm, M.x, 2 * d);
            Mo.y = __shfl_down_sync(fullm, M.y, 2 * d);
            Mo.z = __shfl_down_sync(fullm, M.z, 2 * d);
            Mo.w = __shfl_down_sync(fullm, M.w, 2 * d);
            if (sl + d < 16) {
                A.x = fmaf(M.x, Ao.x, A.x); M.x *= Mo.x;
                A.y = fmaf(M.y, Ao.y, A.y); M.y *= Mo.y;
                A.z = fmaf(M.z, Ao.z, A.z); M.z *= Mo.z;
                A.w = fmaf(M.w, Ao.w, A.w); M.w *= Mo.w;
            }
        }

        // full-chunk transform lives in lanes 0 (k0-3) and 1 (k4-7)
        float4 Af, Mf;
        Af.x = __shfl_sync(fullm, A.x, kg);
        Af.y = __shfl_sync(fullm, A.y, kg);
        Af.z = __shfl_sync(fullm, A.z, kg);
        Af.w = __shfl_sync(fullm, A.w, kg);
        Mf.x = __shfl_sync(fullm, M.x, kg);
        Mf.y = __shfl_sync(fullm, M.y, kg);
        Mf.z = __shfl_sync(fullm, M.z, kg);
        Mf.w = __shfl_sync(fullm, M.w, kg);

        // suffix relative to warp-region end: Asuf = A + M*Ar, Msuf = M*Mr
        float4 s4, Ms;
        s4.x = q4.x - fmaf(M.x, Ar.x, A.x);  Ms.x = M.x * Mr.x;
        s4.y = q4.y - fmaf(M.y, Ar.y, A.y);  Ms.y = M.y * Mr.y;
        s4.z = q4.z - fmaf(M.z, Ar.z, A.z);  Ms.z = M.z * Mr.z;
        s4.w = q4.w - fmaf(M.w, Ar.w, A.w);  Ms.w = M.w * Mr.w;

        const int si = tl * KK + kg * 4;     // coalesced, conflict-free
        *(float4*)(s_ + si) = s4;
        __half2 h01 = __floats2half2_rn(Ms.x, Ms.y);
        __half2 h23 = __floats2half2_rn(Ms.z, Ms.w);
        uint2 hp; hp.x = *(uint32_t*)&h01; hp.y = *(uint32_t*)&h23;
        *(uint2*)(mh + si) = hp;

        // advance running suffix by the full chunk
        Ar.x = fmaf(Mf.x, Ar.x, Af.x);  Mr.x *= Mf.x;
        Ar.y = fmaf(Mf.y, Ar.y, Af.y);  Mr.y *= Mf.y;
        Ar.z = fmaf(Mf.z, Ar.z, Af.z);  Mr.z *= Mf.z;
        Ar.w = fmaf(Mf.w, Ar.w, Af.w);  Mr.w *= Mf.w;
    }

    // warp totals
    if (lane < 2) {
        *(float4*)(wA + w * KK + kg * 4) = Ar;
        *(float4*)(wM + w * KK + kg * 4) = Mr;
    }
    __syncthreads();

    // rank1: CTA total applied to 0 -> DSMEM seed for rank0
    if (rank == 1 && tid < KK) {
        float x = 0.0f;
        #pragma unroll
        for (int ww = NW - 1; ww >= 0; --ww)
            x = fmaf(wM[ww * KK + tid], x, wA[ww * KK + tid]);
        uint32_t laddr = smem_u32(&sXin[tid]);
        uint32_t raddr;
        asm("mapa.shared::cluster.u32 %0, %1, %2;" : "=r"(raddr) : "r"(laddr), "r"(0));
        asm volatile("st.shared::cluster.f32 [%0], %1;" :: "r"(raddr), "f"(x) : "memory");
    }
    asm volatile("barrier.cluster.arrive.aligned;" ::: "memory");
    asm volatile("barrier.cluster.wait.aligned;"   ::: "memory");

    // carry at end of this warp's region: compose later warps onto cluster seed
    float4 x4;
    if (rank == 0) x4 = *(const float4*)(sXin + kg * 4);
    else           x4 = make_float4(0.f, 0.f, 0.f, 0.f);
    #pragma unroll
    for (int ww = NW - 1; ww > 0; --ww) {
        if (ww > w) {
            const float4 a4 = *(const float4*)(wA + ww * KK + kg * 4);
            const float4 m4 = *(const float4*)(wM + ww * KK + kg * 4);
            x4.x = fmaf(m4.x, x4.x, a4.x);
            x4.y = fmaf(m4.y, x4.y, a4.y);
            x4.z = fmaf(m4.z, x4.z, a4.z);
            x4.w = fmaf(m4.w, x4.w, a4.w);
        }
    }

    // Phase 2: loss, d = s - Msuf * x4   (all smem traffic coalesced)
    float lsum = 0.0f;
    #pragma unroll
    for (int ch = 0; ch < NCH; ++ch) {
        const int tl = w * WT + ch * CHT + sl;
        const int si = tl * KK + kg * 4;
        const float4 s4 = *(const float4*)(s_ + si);
        const uint2  hp = *(const uint2*)(mh + si);
        const float2 m01 = __half22float2(*(const __half2*)&hp.x);
        const float2 m23 = __half22float2(*(const __half2*)&hp.y);

        float d, ad;
        d = fmaf(-m01.x, x4.x, s4.x); ad = fabsf(d);
        lsum += (ad < 1.0f) ? 0.5f * d * d : (ad - 0.5f);
        d = fmaf(-m01.y, x4.y, s4.y); ad = fabsf(d);
        lsum += (ad < 1.0f) ? 0.5f * d * d : (ad - 0.5f);
        d = fmaf(-m23.x, x4.z, s4.z); ad = fabsf(d);
        lsum += (ad < 1.0f) ? 0.5f * d * d : (ad - 0.5f);
        d = fmaf(-m23.y, x4.w, s4.w); ad = fabsf(d);
        lsum += (ad < 1.0f) ? 0.5f * d * d : (ad - 0.5f);
    }

    // reduce + atomic
    #pragma unroll
    for (int off = 16; off > 0; off >>= 1)
        lsum += __shfl_down_sync(fullm, lsum, off);
    if (lane == 0) red[w] = lsum;
    __syncthreads();
    if (tid < 32) {
        float v = (tid < NW) ? red[tid] : 0.0f;
        #pragma unroll
        for (int off = 4; off > 0; off >>= 1)
            v += __shfl_down_sync(fullm, v, off);
        if (tid == 0)
            atomicAdd(out, v * (1.0f / 33554432.0f));   // mean over 2048*2048*8
    }
}

extern "C" void kernel_launch(void* const* d_in, const int* in_sizes, int n_in,
                              void* d_out, int out_size)
{
    (void)in_sizes; (void)n_in; (void)out_size;
    const float* q   = (const float*)d_in[0];
    const float* tq  = (const float*)d_in[1];
    const float* tv  = (const float*)d_in[2];
    const float* rw  = (const float*)d_in[3];
    const float* olp = (const float*)d_in[4];
    const float* tlp = (const float*)d_in[5];
    float* out = (float*)d_out;

    cudaFuncSetAttribute(retrace_loss_kernel,
                         cudaFuncAttributeMaxDynamicSharedMemorySize,
                         SMEM_BYTES);

    cudaMemsetAsync(out, 0, sizeof(float));
    retrace_loss_kernel<<<BB * CSZ, 256, SMEM_BYTES>>>(q, tq, tv, rw, olp, tlp, out);
}

// round 7
// speedup vs baseline: 2.3654x; 1.1882x over previous
#include <cuda_runtime.h>
#include <cuda_fp16.h>
#include <cstdint>

#define BB     2048
#define TT     2049
#define SS     2048      // T-1
#define KK     8
#define CSZ    2         // cluster size
#define QT     1024      // timesteps per CTA
#define NTH    512       // threads per CTA
#define NW     16        // warps per CTA
#define WT     64        // timesteps per warp
#define NCH    4         // chunks per warp
#define CHT    16        // timesteps per chunk (2 lanes per t)
#define GAMMA_F 0.99f

// smem: wA,wM [NW*KK] f32 | sXin [KK] | red [NW]
#define SMEM_BYTES (2*NW*KK*4 + KK*4 + NW*4)

__device__ __forceinline__ uint32_t smem_u32(const void* p) {
    uint32_t a;
    asm("{ .reg .u64 t; cvta.to.shared.u64 t, %1; cvt.u32.u64 %0, t; }"
        : "=r"(a) : "l"(p));
    return a;
}

__global__ __launch_bounds__(NTH, 2) __cluster_dims__(CSZ, 1, 1)
void retrace_loss_kernel(const float* __restrict__ q,
                         const float* __restrict__ tq,
                         const float* __restrict__ tv,
                         const float* __restrict__ rw,
                         const float* __restrict__ olp,
                         const float* __restrict__ tlp,
                         float* __restrict__ out)
{
    extern __shared__ char smem[];
    float* wA   = (float*)smem;            // NW*KK
    float* wM   = wA + NW * KK;            // NW*KK
    float* sXin = wM + NW * KK;            // KK
    float* red  = sXin + KK;               // NW

    const int tid  = threadIdx.x;
    const int lane = tid & 31;
    const int w    = tid >> 5;       // warp 0..15, owns t_local [w*64, w*64+64)
    const int sl   = lane >> 1;      // timestep within chunk 0..15
    const int kg   = lane & 1;       // k-group (floats [kg*4, kg*4+4))

    uint32_t rank;
    asm("mov.u32 %0, %%cluster_ctarank;" : "=r"(rank));
    const int b = blockIdx.x >> 1;

    const size_t base3 = (size_t)b * TT * KK;
    const size_t base2 = (size_t)b * TT;
    const unsigned fullm = 0xFFFFFFFFu;

    // register-resident per-element state
    float4 s_reg[NCH];     // q - Asuf (relative to warp-region end)
    uint2  ms_reg[NCH];    // Msuf as 2x half2

    // running suffix relative to warp-region end
    float4 Ar = make_float4(0.f, 0.f, 0.f, 0.f);
    float4 Mr = make_float4(1.f, 1.f, 1.f, 1.f);

    #pragma unroll
    for (int ch = NCH - 1; ch >= 0; --ch) {
        const int tl = w * WT + ch * CHT + sl;          // local timestep
        const int t  = (int)rank * QT + tl;             // timestep in row
        const size_t o0 = base3 + (size_t)t * KK + kg * 4;

        // fully coalesced: warp covers 512 contiguous bytes per LDG.128
        const float4 r4 = *(const float4*)(rw  + o0);
        const float4 q4 = *(const float4*)(q   + o0);
        const float4 v4 = *(const float4*)(tv  + o0 + KK);
        const float4 Q4 = *(const float4*)(tq  + o0 + KK);
        const float4 l4 = *(const float4*)(tlp + o0 + KK);
        const float  ol = olp[base2 + t + 1];

        const bool last = (t == SS - 1);
        const float sgn = last ? 1.0f : -1.0f;
        const float gm  = last ? 0.0f : GAMMA_F;

        float4 A, M;
        { float c = __expf(fminf(l4.x - ol, 0.f));
          A.x = fmaf(GAMMA_F, fmaf(sgn * c, Q4.x, v4.x), r4.x); M.x = gm * c; }
        { float c = __expf(fminf(l4.y - ol, 0.f));
          A.y = fmaf(GAMMA_F, fmaf(sgn * c, Q4.y, v4.y), r4.y); M.y = gm * c; }
        { float c = __expf(fminf(l4.z - ol, 0.f));
          A.z = fmaf(GAMMA_F, fmaf(sgn * c, Q4.z, v4.z), r4.z); M.z = gm * c; }
        { float c = __expf(fminf(l4.w - ol, 0.f));
          A.w = fmaf(GAMMA_F, fmaf(sgn * c, Q4.w, v4.w), r4.w); M.w = gm * c; }

        // warp suffix scan over 16 timesteps (lanes): x_sl = A + M * x_chunkend
        #pragma unroll
        for (int d = 1; d < 16; d <<= 1) {
            float4 Ao, Mo;
            Ao.x = __shfl_down_sync(fullm, A.x, 2 * d);
            Ao.y = __shfl_down_sync(fullm, A.y, 2 * d);
            Ao.z = __shfl_down_sync(fullm, A.z, 2 * d);
            Ao.w = __shfl_down_sync(fullm, A.w, 2 * d);
            Mo.x = __shfl_down_sync(fullm, M.x, 2 * d);
            Mo.y = __shfl_down_sync(fullm, M.y, 2 * d);
            Mo.z = __shfl_down_sync(fullm, M.z, 2 * d);
            Mo.w = __shfl_down_sync(fullm, M.w, 2 * d);
            if (sl + d < 16) {
                A.x = fmaf(M.x, Ao.x, A.x); M.x *= Mo.x;
                A.y = fmaf(M.y, Ao.y, A.y); M.y *= Mo.y;
                A.z = fmaf(M.z, Ao.z, A.z); M.z *= Mo.z;
                A.w = fmaf(M.w, Ao.w, A.w); M.w *= Mo.w;
            }
        }

        // full-chunk transform lives in lanes 0 (k0-3) / 1 (k4-7)
        float4 Af, Mf;
        Af.x = __shfl_sync(fullm, A.x, kg);
        Af.y = __shfl_sync(fullm, A.y, kg);
        Af.z = __shfl_sync(fullm, A.z, kg);
        Af.w = __shfl_sync(fullm, A.w, kg);
        Mf.x = __shfl_sync(fullm, M.x, kg);
        Mf.y = __shfl_sync(fullm, M.y, kg);
        Mf.z = __shfl_sync(fullm, M.z, kg);
        Mf.w = __shfl_sync(fullm, M.w, kg);

        // suffix relative to warp-region end: s = q - (A + M*Ar), Msuf = M*Mr
        float4 s4, Ms;
        s4.x = q4.x - fmaf(M.x, Ar.x, A.x);  Ms.x = M.x * Mr.x;
        s4.y = q4.y - fmaf(M.y, Ar.y, A.y);  Ms.y = M.y * Mr.y;
        s4.z = q4.z - fmaf(M.z, Ar.z, A.z);  Ms.z = M.z * Mr.z;
        s4.w = q4.w - fmaf(M.w, Ar.w, A.w);  Ms.w = M.w * Mr.w;

        s_reg[ch] = s4;
        __half2 h01 = __floats2half2_rn(Ms.x, Ms.y);
        __half2 h23 = __floats2half2_rn(Ms.z, Ms.w);
        ms_reg[ch].x = *(uint32_t*)&h01;
        ms_reg[ch].y = *(uint32_t*)&h23;

        // advance running suffix by the full chunk
        Ar.x = fmaf(Mf.x, Ar.x, Af.x);  Mr.x *= Mf.x;
        Ar.y = fmaf(Mf.y, Ar.y, Af.y);  Mr.y *= Mf.y;
        Ar.z = fmaf(Mf.z, Ar.z, Af.z);  Mr.z *= Mf.z;
        Ar.w = fmaf(Mf.w, Ar.w, Af.w);  Mr.w *= Mf.w;
    }

    // warp totals -> smem
    if (lane < 2) {
        *(float4*)(wA + w * KK + kg * 4) = Ar;
        *(float4*)(wM + w * KK + kg * 4) = Mr;
    }
    __syncthreads();

    // rank1: CTA total applied to 0 -> DSMEM seed for rank0
    if (rank == 1 && tid < KK) {
        float x = 0.0f;
        #pragma unroll
        for (int ww = NW - 1; ww >= 0; --ww)
            x = fmaf(wM[ww * KK + tid], x, wA[ww * KK + tid]);
        uint32_t laddr = smem_u32(&sXin[tid]);
        uint32_t raddr;
        asm("mapa.shared::cluster.u32 %0, %1, %2;" : "=r"(raddr) : "r"(laddr), "r"(0));
        asm volatile("st.shared::cluster.f32 [%0], %1;" :: "r"(raddr), "f"(x) : "memory");
    }
    asm volatile("barrier.cluster.arrive.aligned;" ::: "memory");
    asm volatile("barrier.cluster.wait.aligned;"   ::: "memory");

    // carry at end of this warp's region: compose later warps onto cluster seed
    float4 x4;
    if (rank == 0) x4 = *(const float4*)(sXin + kg * 4);
    else           x4 = make_float4(0.f, 0.f, 0.f, 0.f);
    #pragma unroll
    for (int ww = NW - 1; ww > 0; --ww) {
        if (ww > w) {
            const float4 a4 = *(const float4*)(wA + ww * KK + kg * 4);
            const float4 m4 = *(const float4*)(wM + ww * KK + kg * 4);
            x4.x = fmaf(m4.x, x4.x, a4.x);
            x4.y = fmaf(m4.y, x4.y, a4.y);
            x4.z = fmaf(m4.z, x4.z, a4.z);
            x4.w = fmaf(m4.w, x4.w, a4.w);
        }
    }

    // Phase 2: pure register math: d = s - Msuf * x4
    float lsum = 0.0f;
    #pragma unroll
    for (int ch = 0; ch < NCH; ++ch) {
        const float4 s4 = s_reg[ch];
        const float2 m01 = __half22float2(*(const __half2*)&ms_reg[ch].x);
        const float2 m23 = __half22float2(*(const __half2*)&ms_reg[ch].y);

        float d, ad;
        d = fmaf(-m01.x, x4.x, s4.x); ad = fabsf(d);
        lsum += (ad < 1.0f) ? 0.5f * d * d : (ad - 0.5f);
        d = fmaf(-m01.y, x4.y, s4.y); ad = fabsf(d);
        lsum += (ad < 1.0f) ? 0.5f * d * d : (ad - 0.5f);
        d = fmaf(-m23.x, x4.z, s4.z); ad = fabsf(d);
        lsum += (ad < 1.0f) ? 0.5f * d * d : (ad - 0.5f);
        d = fmaf(-m23.y, x4.w, s4.w); ad = fabsf(d);
        lsum += (ad < 1.0f) ? 0.5f * d * d : (ad - 0.5f);
    }

    // reduce + atomic
    #pragma unroll
    for (int off = 16; off > 0; off >>= 1)
        lsum += __shfl_down_sync(fullm, lsum, off);
    if (lane == 0) red[w] = lsum;
    __syncthreads();
    if (tid < 32) {
        float v = (tid < NW) ? red[tid] : 0.0f;
        #pragma unroll
        for (int off = 8; off > 0; off >>= 1)
            v += __shfl_down_sync(fullm, v, off);
        if (tid == 0)
            atomicAdd(out, v * (1.0f / 33554432.0f));   // mean over 2048*2048*8
    }
}

extern "C" void kernel_launch(void* const* d_in, const int* in_sizes, int n_in,
                              void* d_out, int out_size)
{
    (void)in_sizes; (void)n_in; (void)out_size;
    const float* q   = (const float*)d_in[0];
    const float* tq  = (const float*)d_in[1];
    const float* tv  = (const float*)d_in[2];
    const float* rw  = (const float*)d_in[3];
    const float* olp = (const float*)d_in[4];
    const float* tlp = (const float*)d_in[5];
    float* out = (float*)d_out;

    cudaFuncSetAttribute(retrace_loss_kernel,
                         cudaFuncAttributeMaxDynamicSharedMemorySize,
                         SMEM_BYTES);

    cudaMemsetAsync(out, 0, sizeof(float));
    retrace_loss_kernel<<<BB * CSZ, NTH, SMEM_BYTES>>>(q, tq, tv, rw, olp, tlp, out);
}

// round 8
// speedup vs baseline: 2.4567x; 1.0386x over previous
#include <cuda_runtime.h>
#include <cuda_fp16.h>
#include <cstdint>

#define BB     2048
#define TT     2049
#define SS     2048      // T-1
#define KK     8
#define CSZ    2         // cluster size
#define QT     1024      // timesteps per CTA
#define NTH    512       // threads per CTA
#define NW     16        // warps per CTA
#define WT     64        // timesteps per warp
#define NCH    4         // chunks per warp
#define CHT    16        // timesteps per chunk (2 lanes per t)
#define GAMMA_F 0.99f

// smem: wA,wM [NW*KK] f32 | sXin [KK] | red [NW]
#define SMEM_BYTES (2*NW*KK*4 + KK*4 + NW*4)

__device__ __forceinline__ uint32_t smem_u32(const void* p) {
    uint32_t a;
    asm("{ .reg .u64 t; cvta.to.shared.u64 t, %1; cvt.u32.u64 %0, t; }"
        : "=r"(a) : "l"(p));
    return a;
}

__global__ __launch_bounds__(NTH, 2) __cluster_dims__(CSZ, 1, 1)
void retrace_loss_kernel(const float* __restrict__ q,
                         const float* __restrict__ tq,
                         const float* __restrict__ tv,
                         const float* __restrict__ rw,
                         const float* __restrict__ olp,
                         const float* __restrict__ tlp,
                         float* __restrict__ out)
{
    extern __shared__ char smem[];
    float* wA   = (float*)smem;            // NW*KK
    float* wM   = wA + NW * KK;            // NW*KK
    float* sXin = wM + NW * KK;            // KK
    float* red  = sXin + KK;               // NW

    const int tid  = threadIdx.x;
    const int lane = tid & 31;
    const int w    = tid >> 5;       // warp 0..15, owns t_local [w*64, w*64+64)
    const int sl   = lane >> 1;      // timestep within chunk 0..15
    const int kg   = lane & 1;       // k-group (floats [kg*4, kg*4+4))

    uint32_t rank;
    asm("mov.u32 %0, %%cluster_ctarank;" : "=r"(rank));
    const int b = blockIdx.x >> 1;

    const size_t base3 = (size_t)b * TT * KK;
    const size_t base2 = (size_t)b * TT;
    const unsigned fullm = 0xFFFFFFFFu;

    // register-resident per-element state (relative to warp-region end)
    float4 As_reg[NCH];    // Asuf
    uint2  ms_reg[NCH];    // Msuf as 2x half2

    // running suffix relative to warp-region end
    float4 Ar = make_float4(0.f, 0.f, 0.f, 0.f);
    float4 Mr = make_float4(1.f, 1.f, 1.f, 1.f);

    #pragma unroll
    for (int ch = NCH - 1; ch >= 0; --ch) {
        const int tl = w * WT + ch * CHT + sl;          // local timestep
        const int t  = (int)rank * QT + tl;             // timestep in row
        const size_t o0 = base3 + (size_t)t * KK + kg * 4;

        // fully coalesced streaming loads (no q in phase 1)
        const float4 r4 = __ldcs((const float4*)(rw  + o0));
        const float4 v4 = __ldcs((const float4*)(tv  + o0 + KK));
        const float4 Q4 = __ldcs((const float4*)(tq  + o0 + KK));
        const float4 l4 = __ldcs((const float4*)(tlp + o0 + KK));
        const float  ol = olp[base2 + t + 1];

        const bool last = (t == SS - 1);
        const float sgn = last ? 1.0f : -1.0f;
        const float gm  = last ? 0.0f : GAMMA_F;

        float4 A, M;
        { float c = __expf(fminf(l4.x - ol, 0.f));
          A.x = fmaf(GAMMA_F, fmaf(sgn * c, Q4.x, v4.x), r4.x); M.x = gm * c; }
        { float c = __expf(fminf(l4.y - ol, 0.f));
          A.y = fmaf(GAMMA_F, fmaf(sgn * c, Q4.y, v4.y), r4.y); M.y = gm * c; }
        { float c = __expf(fminf(l4.z - ol, 0.f));
          A.z = fmaf(GAMMA_F, fmaf(sgn * c, Q4.z, v4.z), r4.z); M.z = gm * c; }
        { float c = __expf(fminf(l4.w - ol, 0.f));
          A.w = fmaf(GAMMA_F, fmaf(sgn * c, Q4.w, v4.w), r4.w); M.w = gm * c; }

        // warp suffix scan over 16 timesteps (lanes): x_sl = A + M * x_chunkend
        #pragma unroll
        for (int d = 1; d < 16; d <<= 1) {
            float4 Ao, Mo;
            Ao.x = __shfl_down_sync(fullm, A.x, 2 * d);
            Ao.y = __shfl_down_sync(fullm, A.y, 2 * d);
            Ao.z = __shfl_down_sync(fullm, A.z, 2 * d);
            Ao.w = __shfl_down_sync(fullm, A.w, 2 * d);
            Mo.x = __shfl_down_sync(fullm, M.x, 2 * d);
            Mo.y = __shfl_down_sync(fullm, M.y, 2 * d);
            Mo.z = __shfl_down_sync(fullm, M.z, 2 * d);
            Mo.w = __shfl_down_sync(fullm, M.w, 2 * d);
            if (sl + d < 16) {
                A.x = fmaf(M.x, Ao.x, A.x); M.x *= Mo.x;
                A.y = fmaf(M.y, Ao.y, A.y); M.y *= Mo.y;
                A.z = fmaf(M.z, Ao.z, A.z); M.z *= Mo.z;
                A.w = fmaf(M.w, Ao.w, A.w); M.w *= Mo.w;
            }
        }

        // full-chunk transform lives in lanes 0 (k0-3) / 1 (k4-7)
        float4 Af, Mf;
        Af.x = __shfl_sync(fullm, A.x, kg);
        Af.y = __shfl_sync(fullm, A.y, kg);
        Af.z = __shfl_sync(fullm, A.z, kg);
        Af.w = __shfl_sync(fullm, A.w, kg);
        Mf.x = __shfl_sync(fullm, M.x, kg);
        Mf.y = __shfl_sync(fullm, M.y, kg);
        Mf.z = __shfl_sync(fullm, M.z, kg);
        Mf.w = __shfl_sync(fullm, M.w, kg);

        // suffix relative to warp-region end: Asuf = A + M*Ar, Msuf = M*Mr
        float4 As, Ms;
        As.x = fmaf(M.x, Ar.x, A.x);  Ms.x = M.x * Mr.x;
        As.y = fmaf(M.y, Ar.y, A.y);  Ms.y = M.y * Mr.y;
        As.z = fmaf(M.z, Ar.z, A.z);  Ms.z = M.z * Mr.z;
        As.w = fmaf(M.w, Ar.w, A.w);  Ms.w = M.w * Mr.w;

        As_reg[ch] = As;
        __half2 h01 = __floats2half2_rn(Ms.x, Ms.y);
        __half2 h23 = __floats2half2_rn(Ms.z, Ms.w);
        ms_reg[ch].x = *(uint32_t*)&h01;
        ms_reg[ch].y = *(uint32_t*)&h23;

        // advance running suffix by the full chunk
        Ar.x = fmaf(Mf.x, Ar.x, Af.x);  Mr.x *= Mf.x;
        Ar.y = fmaf(Mf.y, Ar.y, Af.y);  Mr.y *= Mf.y;
        Ar.z = fmaf(Mf.z, Ar.z, Af.z);  Mr.z *= Mf.z;
        Ar.w = fmaf(Mf.w, Ar.w, Af.w);  Mr.w *= Mf.w;
    }

    // warp totals -> smem
    if (lane < 2) {
        *(float4*)(wA + w * KK + kg * 4) = Ar;
        *(float4*)(wM + w * KK + kg * 4) = Mr;
    }
    __syncthreads();

    // issue q loads NOW: they fly during combine + cluster barrier (tail overlap)
    float4 q_reg[NCH];
    #pragma unroll
    for (int ch = 0; ch < NCH; ++ch) {
        const int tl = w * WT + ch * CHT + sl;
        const size_t o0 = base3 + (size_t)((int)rank * QT + tl) * KK + kg * 4;
        q_reg[ch] = __ldcs((const float4*)(q + o0));
    }

    // rank1: CTA total applied to 0 -> DSMEM seed for rank0
    if (rank == 1 && tid < KK) {
        float x = 0.0f;
        #pragma unroll
        for (int ww = NW - 1; ww >= 0; --ww)
            x = fmaf(wM[ww * KK + tid], x, wA[ww * KK + tid]);
        uint32_t laddr = smem_u32(&sXin[tid]);
        uint32_t raddr;
        asm("mapa.shared::cluster.u32 %0, %1, %2;" : "=r"(raddr) : "r"(laddr), "r"(0));
        asm volatile("st.shared::cluster.f32 [%0], %1;" :: "r"(raddr), "f"(x) : "memory");
    }
    asm volatile("barrier.cluster.arrive.aligned;" ::: "memory");
    asm volatile("barrier.cluster.wait.aligned;"   ::: "memory");

    // carry at end of this warp's region: compose later warps onto cluster seed
    float4 x4;
    if (rank == 0) x4 = *(const float4*)(sXin + kg * 4);
    else           x4 = make_float4(0.f, 0.f, 0.f, 0.f);
    #pragma unroll
    for (int ww = NW - 1; ww > 0; --ww) {
        if (ww > w) {
            const float4 a4 = *(const float4*)(wA + ww * KK + kg * 4);
            const float4 m4 = *(const float4*)(wM + ww * KK + kg * 4);
            x4.x = fmaf(m4.x, x4.x, a4.x);
            x4.y = fmaf(m4.y, x4.y, a4.y);
            x4.z = fmaf(m4.z, x4.z, a4.z);
            x4.w = fmaf(m4.w, x4.w, a4.w);
        }
    }

    // Phase 2: d = q - (Asuf + Msuf * x4)
    float lsum = 0.0f;
    #pragma unroll
    for (int ch = 0; ch < NCH; ++ch) {
        const float4 a4 = As_reg[ch];
        const float4 q4 = q_reg[ch];
        const float2 m01 = __half22float2(*(const __half2*)&ms_reg[ch].x);
        const float2 m23 = __half22float2(*(const __half2*)&ms_reg[ch].y);

        float d, ad;
        d = q4.x - fmaf(m01.x, x4.x, a4.x); ad = fabsf(d);
        lsum += (ad < 1.0f) ? 0.5f * d * d : (ad - 0.5f);
        d = q4.y - fmaf(m01.y, x4.y, a4.y); ad = fabsf(d);
        lsum += (ad < 1.0f) ? 0.5f * d * d : (ad - 0.5f);
        d = q4.z - fmaf(m23.x, x4.z, a4.z); ad = fabsf(d);
        lsum += (ad < 1.0f) ? 0.5f * d * d : (ad - 0.5f);
        d = q4.w - fmaf(m23.y, x4.w, a4.w); ad = fabsf(d);
        lsum += (ad < 1.0f) ? 0.5f * d * d : (ad - 0.5f);
    }

    // reduce + atomic
    #pragma unroll
    for (int off = 16; off > 0; off >>= 1)
        lsum += __shfl_down_sync(fullm, lsum, off);
    if (lane == 0) red[w] = lsum;
    __syncthreads();
    if (tid < 32) {
        float v = (tid < NW) ? red[tid] : 0.0f;
        #pragma unroll
        for (int off = 8; off > 0; off >>= 1)
            v += __shfl_down_sync(fullm, v, off);
        if (tid == 0)
            atomicAdd(out, v * (1.0f / 33554432.0f));   // mean over 2048*2048*8
    }
}

extern "C" void kernel_launch(void* const* d_in, const int* in_sizes, int n_in,
                              void* d_out, int out_size)
{
    (void)in_sizes; (void)n_in; (void)out_size;
    const float* q   = (const float*)d_in[0];
    const float* tq  = (const float*)d_in[1];
    const float* tv  = (const float*)d_in[2];
    const float* rw  = (const float*)d_in[3];
    const float* olp = (const float*)d_in[4];
    const float* tlp = (const float*)d_in[5];
    float* out = (float*)d_out;

    cudaFuncSetAttribute(retrace_loss_kernel,
                         cudaFuncAttributeMaxDynamicSharedMemorySize,
                         SMEM_BYTES);

    cudaMemsetAsync(out, 0, sizeof(float));
    retrace_loss_kernel<<<BB * CSZ, NTH, SMEM_BYTES>>>(q, tq, tv, rw, olp, tlp, out);
}